// round 14
// baseline (speedup 1.0000x reference)
#include <cuda_runtime.h>
#include <cstdint>

// patches: [N=128, C=4, P=32, P, P] f32
// vol:     [B=2,  C=4, H=128, H, H] f32
// centers: [N, 3] i32 ; lower = center - 16 (in [0, 96])
// out = 0.5 * (vol + sum of covering patches)   -- gather, one pass, no atomics.
// cp.async stages hit rows into smem; slots are padded with permanent zero quads
// so out-of-window lanes read zeros via a clamped index (no per-lane selects).

#define C_DIM 4
#define P_DIM 32
#define H_DIM 128

// per-patch strides in float4 units
#define PATCH_F4   32768u   // C*P^3/4
#define PC_F4      8192u    // P^3/4   (channel stride)
#define PI_F4      256u     // P^2/4   (i stride)
#define PJ_F4      8u       // P/4     (j stride)

#define S_SLOTS    6        // staged hits per warp per chunk
#define CH_Q       12       // quads per channel in a slot: [Z Z d0..d7 Z Z]
#define SLOT_F4    (C_DIM * CH_Q)          // 48 float4
#define SLOT_BYTES (SLOT_F4 * 16)          // 768 B

// Block = (b, x, y-octave of 8): 2*128*16 = 4096 blocks of 256 threads.
__global__ void __launch_bounds__(256)
pi_fused_kernel(const float4* __restrict__ patches4,
                const float4* __restrict__ vol4,
                const int*    __restrict__ centers,
                float4*       __restrict__ out4)
{
    __shared__ int      s_cnt;
    __shared__ unsigned s_base[64];   // p*PATCH_F4 + dx*PI_F4 (float4 units)
    __shared__ int      s_lo1[64];
    __shared__ int      s_lo2[64];
    __shared__ __align__(16) char s_stage[8 * S_SLOTS * SLOT_BYTES];  // 36.9 KB

    const unsigned blk  = blockIdx.x;
    const unsigned b    = blk >> 11;           // 2048 blocks per batch
    const unsigned rem  = blk & 2047u;
    const unsigned x    = rem >> 4;            // 0..127
    const unsigned y0   = (rem & 15u) << 3;    // 0,8,...,120
    const unsigned lane = threadIdx.x & 31u;
    const unsigned wid  = threadIdx.x >> 5;    // this warp's y = y0 + wid

    const int y = (int)(y0 + wid);
    const size_t cstr = (size_t)H_DIM * H_DIM * (H_DIM / 4);
    const size_t line = (((size_t)(b * C_DIM) * H_DIM + x) * H_DIM + (unsigned)y)
                        * (H_DIM / 4) + lane;

    // vol loads issued first -- in flight through filter + pad-zeroing + staging
    float4 acc0 = __ldg(vol4 + line + 0 * cstr);
    float4 acc1 = __ldg(vol4 + line + 1 * cstr);
    float4 acc2 = __ldg(vol4 + line + 2 * cstr);
    float4 acc3 = __ldg(vol4 + line + 3 * cstr);

    float4* warp_stage4 = (float4*)(s_stage + (size_t)wid * (S_SLOTS * SLOT_BYTES));

    // zero the pad quads ONCE (cp.async never writes them):
    // per slot, per channel: quad offsets {0, 1, 10, 11}  -> 16 pads/slot,
    // 96 pads per warp = 3 per lane.
    {
        const float4 Z0 = make_float4(0.f,0.f,0.f,0.f);
        #pragma unroll
        for (int i = 0; i < 3; i++) {
            unsigned idx  = i * 32u + lane;        // 0..95
            unsigned slot = idx >> 4;              // /16
            unsigned r    = idx & 15u;
            unsigned c    = r >> 2;
            unsigned j    = r & 3u;
            unsigned pos  = (j < 2u) ? j : (8u + j);   // {0,1,10,11}
            warp_stage4[slot * SLOT_F4 + c * CH_Q + pos] = Z0;
        }
    }

    if (threadIdx.x == 0) s_cnt = 0;
    __syncthreads();

    // cooperative filter: threads 0..63 each test one patch of this batch
    if (threadIdx.x < 64u) {
        unsigned n = b * 64u + threadIdx.x;
        int lo0 = centers[n * 3 + 0] - (P_DIM / 2);
        int lo1 = centers[n * 3 + 1] - (P_DIM / 2);
        int lo2 = centers[n * 3 + 2] - (P_DIM / 2);
        unsigned dx = (unsigned)((int)x - lo0);
        bool hit_x = dx < 32u;
        bool hit_y = (unsigned)(lo1 - (int)y0 + 31) < 39u;  // overlaps [y0, y0+7]
        if (hit_x && hit_y) {
            int idx = atomicAdd(&s_cnt, 1);
            s_base[idx] = threadIdx.x * PATCH_F4 + dx * PI_F4;
            s_lo1[idx]  = lo1;
            s_lo2[idx]  = lo2;
        }
    }
    __syncthreads();

    const int ncand = s_cnt;
    const float4* pb = patches4 + (size_t)b * 64u * PATCH_F4;

    const unsigned c_l = lane >> 3;
    const unsigned q_l = lane & 7u;
    // cp.async dest for this lane: slot base + (c*12 + 2 + q) quads
    const unsigned dst0 = (unsigned)__cvta_generic_to_shared(warp_stage4)
                        + (c_l * CH_Q + 2u + q_l) * 16u;

    // consume: qL/qR always in-bounds; pads supply exact zeros
    #define ACCUM_BODY(EX0,EY0,EZ0,EW0)                                        \
        {                                                                       \
            float4 L0 = sl[0*CH_Q + 1 + mc];                                    \
            float4 R0 = sl[0*CH_Q + 2 + mc];                                    \
            float4 L1 = sl[1*CH_Q + 1 + mc];                                    \
            float4 R1 = sl[1*CH_Q + 2 + mc];                                    \
            float4 L2 = sl[2*CH_Q + 1 + mc];                                    \
            float4 R2 = sl[2*CH_Q + 2 + mc];                                    \
            float4 L3 = sl[3*CH_Q + 1 + mc];                                    \
            float4 R3 = sl[3*CH_Q + 2 + mc];                                    \
            acc0.x += EX0(L0,R0); acc0.y += EY0(L0,R0);                         \
            acc0.z += EZ0(L0,R0); acc0.w += EW0(L0,R0);                         \
            acc1.x += EX0(L1,R1); acc1.y += EY0(L1,R1);                         \
            acc1.z += EZ0(L1,R1); acc1.w += EW0(L1,R1);                         \
            acc2.x += EX0(L2,R2); acc2.y += EY0(L2,R2);                         \
            acc2.z += EZ0(L2,R2); acc2.w += EW0(L2,R2);                         \
            acc3.x += EX0(L3,R3); acc3.y += EY0(L3,R3);                         \
            acc3.z += EZ0(L3,R3); acc3.w += EW0(L3,R3);                         \
        }

    #define SEL_RX(L,R) (R.x)
    #define SEL_RY(L,R) (R.y)
    #define SEL_RZ(L,R) (R.z)
    #define SEL_RW(L,R) (R.w)
    #define SEL_LY(L,R) (L.y)
    #define SEL_LZ(L,R) (L.z)
    #define SEL_LW(L,R) (L.w)

    // chunked stage/consume: almost always a single chunk (expected hits ~4)
    int cI = 0;
    while (cI < ncand) {
        // ---- phase 1: stage up to S_SLOTS hit rows via cp.async ----
        int cJ = cI;
        {
            unsigned q = 0;
            #pragma unroll 1
            for (; cJ < ncand && q < S_SLOTS; cJ++) {
                unsigned dy = (unsigned)(y - s_lo1[cJ]);
                if (dy >= 32u) continue;          // warp-uniform
                const float4* gsrc = pb + s_base[cJ] + dy * PJ_F4
                                   + c_l * PC_F4 + q_l;
                asm volatile("cp.async.ca.shared.global [%0], [%1], 16;"
                             :: "r"(dst0 + q * SLOT_BYTES), "l"(gsrc));
                q++;
            }
            asm volatile("cp.async.wait_all;" ::: "memory");
            __syncwarp();
        }

        // ---- phase 2: consume staged rows from smem ----
        {
            unsigned q = 0;
            #pragma unroll 1
            for (int k = cI; k < cJ; k++) {
                unsigned dy = (unsigned)(y - s_lo1[k]);
                if (dy >= 32u) continue;          // warp-uniform
                const int lo2 = s_lo2[k];
                int m = (int)lane - (lo2 >> 2);
                int mc = m < -1 ? -1 : (m > 9 ? 9 : m);   // 2 IMNMX, no selects
                const unsigned s = (unsigned)lo2 & 3u;    // warp-uniform
                const float4* sl = warp_stage4 + q * SLOT_F4;
                switch (s) {                       // warp-uniform
                case 0u:  ACCUM_BODY(SEL_RX, SEL_RY, SEL_RZ, SEL_RW) break;
                case 1u:  ACCUM_BODY(SEL_LW, SEL_RX, SEL_RY, SEL_RZ) break;
                case 2u:  ACCUM_BODY(SEL_LZ, SEL_LW, SEL_RX, SEL_RY) break;
                default:  ACCUM_BODY(SEL_LY, SEL_LZ, SEL_LW, SEL_RX) break;
                }
                q++;
            }
        }
        cI = cJ;
        __syncwarp();   // stage buffer reuse safety (rare multi-chunk case)
    }

    // epilogue: out = 0.5 * acc   (acc already contains vol + patch sums)
    #define EPI(C, ACC)                                                         \
        {                                                                       \
            size_t o = line + (size_t)(C) * cstr;                               \
            float4 rr;                                                          \
            rr.x = ACC.x * 0.5f;                                                \
            rr.y = ACC.y * 0.5f;                                                \
            rr.z = ACC.z * 0.5f;                                                \
            rr.w = ACC.w * 0.5f;                                                \
            out4[o] = rr;                                                       \
        }
    EPI(0, acc0)
    EPI(1, acc1)
    EPI(2, acc2)
    EPI(3, acc3)
}

extern "C" void kernel_launch(void* const* d_in, const int* in_sizes, int n_in,
                              void* d_out, int out_size) {
    const float4* patches = (const float4*)d_in[0];
    const float4* vol     = (const float4*)d_in[1];
    const int*    centers = (const int*)d_in[2];
    float4*       out     = (float4*)d_out;

    // 4096 blocks: (2 batches) x (128 x) x (16 y-octaves), 256 threads each
    pi_fused_kernel<<<4096, 256>>>(patches, vol, centers, out);
}

// round 15
// speedup vs baseline: 1.0395x; 1.0395x over previous
#include <cuda_runtime.h>
#include <cstdint>

// patches: [N=128, C=4, P=32, P, P] f32
// vol:     [B=2,  C=4, H=128, H, H] f32
// centers: [N, 3] i32 ; lower = center - 16 (in [0, 96])
// out = 0.5 * (vol + sum of covering patches)   -- gather, one pass, no atomics.
// R13 structure (cp.async chunked staging + predicated selects) with ALL
// indexing in 32 bits (total elems < 2^32) to cut register pressure naturally.

#define C_DIM 4
#define P_DIM 32
#define H_DIM 128

// per-patch strides in float4 units
#define PATCH_F4   32768u   // C*P^3/4
#define PC_F4      8192u    // P^3/4   (channel stride)
#define PI_F4      256u     // P^2/4   (i stride)
#define PJ_F4      8u       // P/4     (j stride)

#define CSTR_F4    524288u  // H^3/4   (vol/out channel stride in float4)

#define S_SLOTS    8        // staged hits per warp per chunk
#define SLOT_BYTES 512      // 4 channels x 128B row

// Block = (b, x, y-octave of 8): 2*128*16 = 4096 blocks of 256 threads.
__global__ void __launch_bounds__(256)
pi_fused_kernel(const float4* __restrict__ patches4,
                const float4* __restrict__ vol4,
                const int*    __restrict__ centers,
                float4*       __restrict__ out4)
{
    __shared__ int      s_cnt;
    __shared__ unsigned s_base[64];   // p*PATCH_F4 + dx*PI_F4 (float4 units)
    __shared__ int      s_lo1[64];
    __shared__ int      s_lo2[64];
    __shared__ __align__(16) char s_stage[8 * S_SLOTS * SLOT_BYTES];  // 32 KB

    const unsigned blk  = blockIdx.x;
    const unsigned b    = blk >> 11;           // 2048 blocks per batch
    const unsigned rem  = blk & 2047u;
    const unsigned x    = rem >> 4;            // 0..127
    const unsigned y0   = (rem & 15u) << 3;    // 0,8,...,120
    const unsigned lane = threadIdx.x & 31u;
    const unsigned wid  = threadIdx.x >> 5;    // this warp's y = y0 + wid

    const int y = (int)(y0 + wid);
    // 32-bit element indexing: max index = 2*4*128^3/4 = 4.19M << 2^32
    const unsigned line = ((b * C_DIM * H_DIM + x) * H_DIM + (unsigned)y)
                          * (H_DIM / 4) + lane;

    // vol loads issued first -- in flight through filter + staging
    float4 acc0 = __ldg(vol4 + line + 0u * CSTR_F4);
    float4 acc1 = __ldg(vol4 + line + 1u * CSTR_F4);
    float4 acc2 = __ldg(vol4 + line + 2u * CSTR_F4);
    float4 acc3 = __ldg(vol4 + line + 3u * CSTR_F4);

    if (threadIdx.x == 0) s_cnt = 0;
    __syncthreads();

    // cooperative filter: threads 0..63 each test one patch of this batch
    if (threadIdx.x < 64u) {
        unsigned n = b * 64u + threadIdx.x;
        int lo0 = centers[n * 3 + 0] - (P_DIM / 2);
        int lo1 = centers[n * 3 + 1] - (P_DIM / 2);
        int lo2 = centers[n * 3 + 2] - (P_DIM / 2);
        unsigned dx = (unsigned)((int)x - lo0);
        bool hit_x = dx < 32u;
        bool hit_y = (unsigned)(lo1 - (int)y0 + 31) < 39u;  // overlaps [y0, y0+7]
        if (hit_x && hit_y) {
            int idx = atomicAdd(&s_cnt, 1);
            s_base[idx] = threadIdx.x * PATCH_F4 + dx * PI_F4;
            s_lo1[idx]  = lo1;
            s_lo2[idx]  = lo2;
        }
    }
    __syncthreads();

    const int ncand = s_cnt;
    const float4 Z = make_float4(0.f,0.f,0.f,0.f);
    const float4* pb = patches4 + b * (64u * PATCH_F4);   // 64*PATCH_F4 = 2^21

    char* warp_stage = s_stage + wid * (S_SLOTS * SLOT_BYTES);
    const unsigned c_l = lane >> 3;
    const unsigned q_l = lane & 7u;
    const unsigned dst0 = (unsigned)__cvta_generic_to_shared(warp_stage) + lane * 16u;

    #define ACCUM_BODY(EX0,EY0,EZ0,EW0)                                        \
        {                                                                       \
            float4 L0 = vL ? sl[0*8 + (m-1)] : Z;                               \
            float4 R0 = vR ? sl[0*8 + m]     : Z;                               \
            float4 L1 = vL ? sl[1*8 + (m-1)] : Z;                               \
            float4 R1 = vR ? sl[1*8 + m]     : Z;                               \
            float4 L2 = vL ? sl[2*8 + (m-1)] : Z;                               \
            float4 R2 = vR ? sl[2*8 + m]     : Z;                               \
            float4 L3 = vL ? sl[3*8 + (m-1)] : Z;                               \
            float4 R3 = vR ? sl[3*8 + m]     : Z;                               \
            acc0.x += EX0(L0,R0); acc0.y += EY0(L0,R0);                         \
            acc0.z += EZ0(L0,R0); acc0.w += EW0(L0,R0);                         \
            acc1.x += EX0(L1,R1); acc1.y += EY0(L1,R1);                         \
            acc1.z += EZ0(L1,R1); acc1.w += EW0(L1,R1);                         \
            acc2.x += EX0(L2,R2); acc2.y += EY0(L2,R2);                         \
            acc2.z += EZ0(L2,R2); acc2.w += EW0(L2,R2);                         \
            acc3.x += EX0(L3,R3); acc3.y += EY0(L3,R3);                         \
            acc3.z += EZ0(L3,R3); acc3.w += EW0(L3,R3);                         \
        }

    #define SEL_RX(L,R) (R.x)
    #define SEL_RY(L,R) (R.y)
    #define SEL_RZ(L,R) (R.z)
    #define SEL_RW(L,R) (R.w)
    #define SEL_LY(L,R) (L.y)
    #define SEL_LZ(L,R) (L.z)
    #define SEL_LW(L,R) (L.w)

    // chunked stage/consume: almost always a single chunk (expected hits ~4)
    int cI = 0;
    while (cI < ncand) {
        // ---- phase 1: stage up to S_SLOTS hit rows via cp.async ----
        int cJ = cI;
        {
            unsigned q = 0;
            #pragma unroll 1
            for (; cJ < ncand && q < S_SLOTS; cJ++) {
                unsigned dy = (unsigned)(y - s_lo1[cJ]);
                if (dy >= 32u) continue;          // warp-uniform
                const float4* gsrc = pb + (s_base[cJ] + dy * PJ_F4
                                   + c_l * PC_F4 + q_l);
                asm volatile("cp.async.ca.shared.global [%0], [%1], 16;"
                             :: "r"(dst0 + q * SLOT_BYTES), "l"(gsrc));
                q++;
            }
            asm volatile("cp.async.wait_all;" ::: "memory");
            __syncwarp();
        }

        // ---- phase 2: consume staged rows from smem ----
        {
            unsigned q = 0;
            #pragma unroll 1
            for (int k = cI; k < cJ; k++) {
                unsigned dy = (unsigned)(y - s_lo1[k]);
                if (dy >= 32u) continue;          // warp-uniform
                const int lo2 = s_lo2[k];
                const int m   = (int)lane - (lo2 >> 2);
                const unsigned s = (unsigned)lo2 & 3u;
                const bool vL = (unsigned)(m - 1) < 8u;
                const bool vR = (unsigned)m < 8u;
                const float4* sl = (const float4*)(warp_stage + q * SLOT_BYTES);
                switch (s) {                       // warp-uniform
                case 0u:  ACCUM_BODY(SEL_RX, SEL_RY, SEL_RZ, SEL_RW) break;
                case 1u:  ACCUM_BODY(SEL_LW, SEL_RX, SEL_RY, SEL_RZ) break;
                case 2u:  ACCUM_BODY(SEL_LZ, SEL_LW, SEL_RX, SEL_RY) break;
                default:  ACCUM_BODY(SEL_LY, SEL_LZ, SEL_LW, SEL_RX) break;
                }
                q++;
            }
        }
        cI = cJ;
        __syncwarp();   // stage buffer reuse safety (rare multi-chunk case)
    }

    // epilogue: out = 0.5 * acc   (acc already contains vol + patch sums)
    #define EPI(C, ACC)                                                         \
        {                                                                       \
            unsigned o = line + (unsigned)(C) * CSTR_F4;                        \
            float4 rr;                                                          \
            rr.x = ACC.x * 0.5f;                                                \
            rr.y = ACC.y * 0.5f;                                                \
            rr.z = ACC.z * 0.5f;                                                \
            rr.w = ACC.w * 0.5f;                                                \
            out4[o] = rr;                                                       \
        }
    EPI(0, acc0)
    EPI(1, acc1)
    EPI(2, acc2)
    EPI(3, acc3)
}

extern "C" void kernel_launch(void* const* d_in, const int* in_sizes, int n_in,
                              void* d_out, int out_size) {
    const float4* patches = (const float4*)d_in[0];
    const float4* vol     = (const float4*)d_in[1];
    const int*    centers = (const int*)d_in[2];
    float4*       out     = (float4*)d_out;

    // 4096 blocks: (2 batches) x (128 x) x (16 y-octaves), 256 threads each
    pi_fused_kernel<<<4096, 256>>>(patches, vol, centers, out);
}